// round 1
// baseline (speedup 1.0000x reference)
#include <cuda_runtime.h>
#include <math.h>

#define NFFT   512
#define HOP    480
#define NBINS  257
#define BATCH  8
#define LSIG   88200
#define NT     184
#define NBLK   (BATCH * NT)   // 1472
#define NTHREADS 288

__device__ float g_bark[NBINS];
__device__ float g_ath[NBINS];
__device__ float g_partial[NBLK];

// ---------------------------------------------------------------------------
// Precompute bark scale and ATH (absolute threshold of hearing) in fp64 to
// match the numpy fp64 constants exactly (then cast to f32 like the ref).
// ---------------------------------------------------------------------------
__global__ void init_consts_kernel() {
    int f = threadIdx.x;
    if (f < NBINS) {
        double freq = (double)f * 44100.0 / (double)NFFT;
        double r = freq / 7500.0;
        double bark = 13.0 * atan(0.00076 * freq) + 3.5 * atan(r * r);
        double fm = freq > 1e-6 ? freq : 1e-6;
        double fk = fm / 1000.0;
        double ath_db = 3.64 * pow(fk, -0.8)
                      - 6.5 * exp(-0.6 * (fk - 3.3) * (fk - 3.3))
                      + 0.001 * fk * fk * fk * fk;
        if (ath_db > 100.0) ath_db = 100.0;
        if (ath_db < -100.0) ath_db = -100.0;
        double ath = pow(10.0, ath_db / 10.0);
        if (ath < 1e-12) ath = 1e-12;
        g_bark[f] = (float)bark;
        g_ath[f]  = (float)ath;
    }
}

// ---------------------------------------------------------------------------
// One block per (b, t) frame.  288 threads:
//   threads 0..255  : DFT bins 0..255 (chunked rotation recurrence)
//   threads 256..287: bin 256 (Nyquist) via strided sum + warp reduce
// Then the psychoacoustic pipeline, all in shared memory, O(F) masking via
// prefix/suffix max scans in log10 domain.
// ---------------------------------------------------------------------------
__global__ __launch_bounds__(NTHREADS) void pam_frame_kernel(
    const float* __restrict__ pred, const float* __restrict__ tgt)
{
    __shared__ float2 fr[NFFT];        // (windowed pred, windowed target)
    __shared__ float powP[NBINS];
    __shared__ float powT[NBINS];
    __shared__ float dbv[NBINS];
    __shared__ float Am[NBINS];        // prefix-max of L + 1.7*bark (tonal only)
    __shared__ float Bm[NBINS];        // suffix-max of L - 2.7*bark (tonal only)
    __shared__ float red[NTHREADS];

    const int t   = blockIdx.x;
    const int b   = blockIdx.y;
    const int tid = threadIdx.x;

    const float* xp = pred + b * LSIG;
    const float* xt = tgt  + b * LSIG;

    // ---- load frame with reflect padding, apply periodic Hann window ----
    for (int n = tid; n < NFFT; n += NTHREADS) {
        int j = t * HOP + n - (NFFT / 2);
        if (j < 0) j = -j;
        if (j >= LSIG) j = 2 * LSIG - 2 - j;
        float w = 0.5f * (1.0f - cospif((float)n * (1.0f / 256.0f)));
        fr[n] = make_float2(xp[j] * w, xt[j] * w);
    }
    __syncthreads();

    // ---- DFT ----
    if (tid < 256) {
        const int k = tid;
        float sn, cs;  // per-step rotation e^{i*2*pi*k/512}
        sincospif((float)k * (1.0f / 256.0f), &sn, &cs);
        float rp = 0.0f, ip = 0.0f, rt = 0.0f, it = 0.0f;
        #pragma unroll 1
        for (int c = 0; c < 8; c++) {
            int m0 = (k * (c * 64)) & 511;          // reseed twiddle exactly
            float si, cr;
            sincospif((float)m0 * (1.0f / 256.0f), &si, &cr);
            #pragma unroll 8
            for (int i = 0; i < 64; i++) {
                float2 z = fr[c * 64 + i];
                rp = fmaf(cr, z.x, rp);  ip = fmaf(si, z.x, ip);
                rt = fmaf(cr, z.y, rt);  it = fmaf(si, z.y, it);
                float nc = cr * cs - si * sn;
                float ns = si * cs + cr * sn;
                cr = nc; si = ns;
            }
        }
        powP[k] = rp * rp + ip * ip + 1e-12f;
        powT[k] = rt * rt + it * it + 1e-12f;
    } else {
        // Nyquist bin: X[256] = sum x[n]*(-1)^n  (imag = 0)
        int lane = tid - 256;
        float sp = 0.0f, st = 0.0f;
        for (int n = lane; n < NFFT; n += 32) {
            float2 z = fr[n];
            sp += z.x; st += z.y;
        }
        if (lane & 1) { sp = -sp; st = -st; }   // stride 32 keeps parity fixed
        for (int off = 16; off > 0; off >>= 1) {
            sp += __shfl_down_sync(0xffffffffu, sp, off);
            st += __shfl_down_sync(0xffffffffu, st, off);
        }
        if (lane == 0) {
            powP[256] = sp * sp + 1e-12f;
            powT[256] = st * st + 1e-12f;
        }
    }
    __syncthreads();

    // ---- psd in dB ----
    float mydb = 0.0f, mybark = 0.0f, myath = 0.0f;
    if (tid < NBINS) {
        mydb   = 10.0f * log10f(powT[tid]);
        dbv[tid] = mydb;
        mybark = g_bark[tid];
        myath  = g_ath[tid];
    }
    __syncthreads();

    // ---- tonal peaks and log-domain masker terms ----
    if (tid < NBINS) {
        bool tonal = false;
        if (tid >= 1 && tid <= NBINS - 2) {
            tonal = (mydb > dbv[tid - 1]) && (mydb > dbv[tid + 1]) && (mydb >= -40.0f);
        }
        float L = mydb * 0.1f;                 // log10(masker power)
        Am[tid] = tonal ? (L + 1.7f * mybark) : -1e30f;
        Bm[tid] = tonal ? (L - 2.7f * mybark) : -1e30f;
    }
    __syncthreads();

    // ---- Hillis-Steele prefix-max (Am) and suffix-max (Bm) over 257 bins ----
    for (int off = 1; off < NBINS; off <<= 1) {
        float a = -1e30f, bb = -1e30f;
        if (tid < NBINS) {
            a = Am[tid];
            if (tid >= off) a = fmaxf(a, Am[tid - off]);
            bb = Bm[tid];
            if (tid + off < NBINS) bb = fmaxf(bb, Bm[tid + off]);
        }
        __syncthreads();
        if (tid < NBINS) { Am[tid] = a; Bm[tid] = bb; }
        __syncthreads();
    }

    // ---- masking, weights, error, per-thread contribution ----
    float contrib = 0.0f;
    if (tid < NBINS) {
        float mlog = fmaxf(Am[tid] - 1.7f * mybark,
                           Bm[tid] + 2.7f * mybark);
        float masking = exp2f(mlog * 3.3219280948873623f);  // 10^mlog
        float combined = masking + myath;
        float pt = powT[tid];
        float w  = log10f(pt / (combined + 1e-12f) + 1.0f);
        float mp = sqrtf(powP[tid] + 1e-12f);
        float mt = sqrtf(pt + 1e-12f);
        float d  = mp - mt;
        contrib = w * d * d;
    }

    // ---- block reduction (288 -> 1) ----
    red[tid] = contrib;
    __syncthreads();
    if (tid < 32) red[tid] += red[tid + 256];
    __syncthreads();
    for (int s = 128; s >= 1; s >>= 1) {
        if (tid < s) red[tid] += red[tid + s];
        __syncthreads();
    }
    if (tid == 0) g_partial[b * NT + t] = red[0];
}

// ---------------------------------------------------------------------------
// Deterministic final reduction: 1472 partials -> mean
// ---------------------------------------------------------------------------
__global__ void final_reduce_kernel(float* __restrict__ out) {
    __shared__ float red[512];
    int tid = threadIdx.x;
    float s = 0.0f;
    for (int i = tid; i < NBLK; i += 512) s += g_partial[i];
    red[tid] = s;
    __syncthreads();
    for (int st = 256; st >= 1; st >>= 1) {
        if (tid < st) red[tid] += red[tid + st];
        __syncthreads();
    }
    if (tid == 0) out[0] = red[0] * (1.0f / (float)(BATCH * NBINS * NT));
}

extern "C" void kernel_launch(void* const* d_in, const int* in_sizes, int n_in,
                              void* d_out, int out_size) {
    const float* pred = (const float*)d_in[0];
    const float* tgt  = (const float*)d_in[1];
    float* out = (float*)d_out;

    init_consts_kernel<<<1, NTHREADS>>>();
    dim3 grid(NT, BATCH);
    pam_frame_kernel<<<grid, NTHREADS>>>(pred, tgt);
    final_reduce_kernel<<<1, 512>>>(out);
}

// round 3
// speedup vs baseline: 3.7273x; 3.7273x over previous
#include <cuda_runtime.h>
#include <math.h>

#define NFFT   512
#define HOP    480
#define NBINS  257
#define BATCH  8
#define LSIG   88200
#define NT     184
#define NBLK   (BATCH * NT)   // 1472
#define NTHREADS 288          // 9 warps: 256 FFT lanes + bin 256

__device__ float g_partial[NBLK];
__device__ unsigned int g_count = 0;

__global__ __launch_bounds__(NTHREADS) void pam_frame_kernel(
    const float* __restrict__ pred, const float* __restrict__ tgt,
    float* __restrict__ out)
{
    __shared__ float2 Z[NFFT];         // packed complex frame (pred + i*target)
    __shared__ float dbv[NBINS];
    __shared__ float sB[NBINS];        // B-term for reversed scan
    __shared__ float sSuf[NBINS];      // suffix-max results
    __shared__ float awtot[9], bwtot[9];
    __shared__ float redw[16];
    __shared__ int   s_last;

    const int t    = blockIdx.x;
    const int b    = blockIdx.y;
    const int tid  = threadIdx.x;
    const int lane = tid & 31;
    const int wrp  = tid >> 5;

    const float* xp = pred + b * LSIG;
    const float* xt = tgt  + b * LSIG;

    // ---- load frame (reflect pad, periodic Hann), bit-reversed into Z ----
    for (int n = tid; n < NFFT; n += NTHREADS) {
        int j = t * HOP + n - (NFFT / 2);
        if (j < 0) j = -j;
        if (j >= LSIG) j = 2 * LSIG - 2 - j;
        float w = 0.5f * (1.0f - cospif((float)n * (1.0f / 256.0f)));
        int rn = (int)(__brev((unsigned)n) >> 23);
        Z[rn] = make_float2(xp[j] * w, xt[j] * w);
    }
    __syncthreads();

    // ---- iterative radix-2 DIT FFT, 9 stages ----
    #pragma unroll
    for (int s = 0; s < 9; s++) {
        if (tid < 256) {
            int half = 1 << s;
            int pos  = tid & (half - 1);
            int i0 = ((tid >> s) << (s + 1)) + pos;
            int i1 = i0 + half;
            float invhalf = __int_as_float((127 - s) << 23);  // exact 2^-s
            float sw, cw;
            sincospif((float)pos * invhalf, &sw, &cw);        // angle = pi*pos/half
            float2 a = Z[i0], v = Z[i1];
            float tr = cw * v.x + sw * v.y;     // (cw - i*sw) * v
            float ti = cw * v.y - sw * v.x;
            // thread exclusively owns (i0,i1) within a stage: safe to write
            Z[i0] = make_float2(a.x + tr, a.y + ti);
            Z[i1] = make_float2(a.x - tr, a.y - ti);
        }
        __syncthreads();
    }

    // ---- unpack two real spectra + psychoacoustic constants (fp32) ----
    float powP = 0.f, powT = 0.f, mydb = 0.f, mybark = 0.f, myath = 0.f;
    if (tid < NBINS) {
        const int k = tid;
        float2 zk = Z[k];
        float2 zc = Z[(NFFT - k) & (NFFT - 1)];
        float prx = 0.5f * (zk.x + zc.x), pry = 0.5f * (zk.y - zc.y);
        float trx = 0.5f * (zk.y + zc.y), try_ = 0.5f * (zc.x - zk.x);
        powP = prx * prx + pry * pry + 1e-12f;
        powT = trx * trx + try_ * try_ + 1e-12f;
        mydb = 10.0f * log10f(powT);
        dbv[k] = mydb;

        float freq = (float)k * (44100.0f / 512.0f);
        float r = freq * (1.0f / 7500.0f);
        mybark = 13.0f * atanf(0.00076f * freq) + 3.5f * atanf(r * r);
        float fk = fmaxf(freq, 1e-6f) * 1e-3f;
        float ath_db = 3.64f * powf(fk, -0.8f)
                     - 6.5f * expf(-0.6f * (fk - 3.3f) * (fk - 3.3f))
                     + 0.001f * fk * fk * fk * fk;
        ath_db = fminf(fmaxf(ath_db, -100.0f), 100.0f);
        myath = fmaxf(exp10f(ath_db * 0.1f), 1e-12f);
    }
    __syncthreads();

    // ---- tonal peaks, log-domain masker terms ----
    float aval = -1e30f, bval = -1e30f;
    if (tid < NBINS) {
        bool tonal = false;
        if (tid >= 1 && tid <= NBINS - 2)
            tonal = (mydb > dbv[tid - 1]) && (mydb > dbv[tid + 1]) && (mydb >= -40.0f);
        if (tonal) {
            float L = mydb * 0.1f;
            aval = L + 1.7f * mybark;
            bval = L - 2.7f * mybark;
        }
        sB[tid] = bval;
    }

    // warp-level inclusive prefix-max of aval (thread order == bin order)
    float av = aval;
    #pragma unroll
    for (int off = 1; off < 32; off <<= 1) {
        float o = __shfl_up_sync(0xffffffffu, av, off);
        if (lane >= off) av = fmaxf(av, o);
    }
    if (wrp < 8) { if (lane == 31) awtot[wrp] = av; }
    else         { if (lane == 0)  awtot[8]  = av; }
    __syncthreads();   // sB fully written, awtot done

    // reversed-order scan of bval -> suffix-max
    const int ri = NBINS - 1 - tid;           // 256-tid (valid only for tid<NBINS)
    float bv = (tid < NBINS) ? sB[ri] : -1e30f;
    #pragma unroll
    for (int off = 1; off < 32; off <<= 1) {
        float o = __shfl_up_sync(0xffffffffu, bv, off);
        if (lane >= off) bv = fmaxf(bv, o);
    }
    if (wrp < 8) { if (lane == 31) bwtot[wrp] = bv; }
    else         { if (lane == 0)  bwtot[8]  = bv; }
    __syncthreads();

    // combine warp totals; publish suffix-max (barrier kept block-uniform)
    float Apre = -1e30f;
    if (tid < NBINS) {
        float aoff = -1e30f, boff = -1e30f;
        #pragma unroll
        for (int j = 0; j < 8; j++) {
            if (j < wrp) {
                aoff = fmaxf(aoff, awtot[j]);
                boff = fmaxf(boff, bwtot[j]);
            }
        }
        Apre = fmaxf(av, aoff);                // prefix-max at bin tid
        sSuf[ri] = fmaxf(bv, boff);            // suffix-max at bin ri
    }
    __syncthreads();

    // ---- masking, weights, error ----
    float contrib = 0.0f;
    if (tid < NBINS) {
        float Bsuf = sSuf[tid];
        float mlog = fmaxf(Apre - 1.7f * mybark, Bsuf + 2.7f * mybark);
        float masking = exp2f(mlog * 3.3219280948873623f);   // 10^mlog
        float combined = masking + myath;
        float w  = log10f(powT / (combined + 1e-12f) + 1.0f);
        float mp = sqrtf(powP + 1e-12f);
        float mt = sqrtf(powT + 1e-12f);
        float d  = mp - mt;
        contrib = w * d * d;
    }

    // ---- block reduction via shfl ----
    float v = contrib;
    #pragma unroll
    for (int off = 16; off > 0; off >>= 1)
        v += __shfl_down_sync(0xffffffffu, v, off);
    if (lane == 0) redw[wrp] = v;
    __syncthreads();
    if (tid < 16) {
        float s2 = (tid < 9) ? redw[tid] : 0.0f;
        #pragma unroll
        for (int off = 8; off > 0; off >>= 1)
            s2 += __shfl_down_sync(0xffffu, s2, off);
        if (tid == 0) g_partial[b * NT + t] = s2;
    }

    // ---- last block performs the deterministic global reduction ----
    __threadfence();
    if (tid == 0) {
        unsigned r = atomicAdd(&g_count, 1u);
        s_last = (r == NBLK - 1) ? 1 : 0;
    }
    __syncthreads();
    if (s_last) {                                // block-uniform condition
        float s = 0.0f;
        for (int i = tid; i < NBLK; i += NTHREADS) s += g_partial[i];
        #pragma unroll
        for (int off = 16; off > 0; off >>= 1)
            s += __shfl_down_sync(0xffffffffu, s, off);
        if (lane == 0) redw[wrp] = s;
        __syncthreads();
        if (tid < 16) {
            float s2 = (tid < 9) ? redw[tid] : 0.0f;
            #pragma unroll
            for (int off = 8; off > 0; off >>= 1)
                s2 += __shfl_down_sync(0xffffu, s2, off);
            if (tid == 0) {
                out[0] = s2 * (1.0f / (float)(BATCH * NBINS * NT));
                g_count = 0;   // reset for next graph replay
            }
        }
    }
}

extern "C" void kernel_launch(void* const* d_in, const int* in_sizes, int n_in,
                              void* d_out, int out_size) {
    const float* pred = (const float*)d_in[0];
    const float* tgt  = (const float*)d_in[1];
    float* out = (float*)d_out;
    dim3 grid(NT, BATCH);
    pam_frame_kernel<<<grid, NTHREADS>>>(pred, tgt, out);
}